// round 2
// baseline (speedup 1.0000x reference)
#include <cuda_runtime.h>
#include <math.h>

// Problem constants (fixed by the dataset)
#define BB 2
#define NN 50000
#define DD 128
#define EE 500000
#define ROWS (BB * NN)          // 100000 node-rows total

// Scratch (static device globals — no runtime allocation)
__device__ float g_hm[ROWS * DD];   // h @ msg_W            (51.2 MB)
__device__ float g_hg[ROWS * DD];   // sigmoid(h @ gate_W)  (51.2 MB)
__device__ float g_agg[ROWS * DD];  // scatter-add target   (51.2 MB)

// Shared memory layout for both GEMM kernels:
//   Ash: [128 k][132 m]  (transposed A tile, padded)   = 16896 floats
//   Wsh: K1: [128 k][256 n] ; K3: [256 k][128 n]       = 32768 floats
#define ASH_STRIDE 132
#define SMEM_BYTES ((128 * ASH_STRIDE + 128 * 256) * 4)  // 198656 B

// ---------------------------------------------------------------------------
// Kernel 1: per-node precompute.
//   hm = h @ msg_W ; hg = sigmoid(h @ gate_W)
// GEMM M=ROWS, N=256 (msg cols 0..127, gate cols 128..255), K=128.
// 512 threads, block tile 128x256, thread tile 8x8.
// ---------------------------------------------------------------------------
__global__ __launch_bounds__(512) void node_pre_kernel(
    const float* __restrict__ h,
    const float* __restrict__ msg_W,
    const float* __restrict__ gate_W)
{
    extern __shared__ float sh[];
    float* Ash = sh;                      // [128][132]
    float* Wsh = sh + 128 * ASH_STRIDE;   // [128][256]

    const int tid = threadIdx.x;
    const int m0  = blockIdx.x * 128;

    // Load W (both matrices side by side): 128*64 float4 total
    {
        const float4* mw4 = (const float4*)msg_W;   // [128][32]
        const float4* gw4 = (const float4*)gate_W;  // [128][32]
        float4* W4 = (float4*)Wsh;                   // [128][64]
        for (int i = tid; i < 128 * 32; i += 512) {
            int k = i >> 5, c = i & 31;
            W4[k * 64 + c]      = mw4[i];
            W4[k * 64 + 32 + c] = gw4[i];
        }
    }

    // Load A tile transposed: Ash[k][m] = h[m0+m][k]
    {
        const float4* h4 = (const float4*)h;        // [ROWS][32]
        for (int i = tid; i < 128 * 32; i += 512) {
            int m = i >> 5, c = i & 31;
            int row = m0 + m;
            float4 v = (row < ROWS) ? h4[row * 32 + c]
                                    : make_float4(0.f, 0.f, 0.f, 0.f);
            int k = c * 4;
            Ash[(k + 0) * ASH_STRIDE + m] = v.x;
            Ash[(k + 1) * ASH_STRIDE + m] = v.y;
            Ash[(k + 2) * ASH_STRIDE + m] = v.z;
            Ash[(k + 3) * ASH_STRIDE + m] = v.w;
        }
    }
    __syncthreads();

    const int tn = tid & 31;   // 32 col-groups of 8 -> 256 cols
    const int tm = tid >> 5;   // 16 row-groups of 8 -> 128 rows

    float acc[8][8];
#pragma unroll
    for (int i = 0; i < 8; i++)
#pragma unroll
        for (int j = 0; j < 8; j++) acc[i][j] = 0.f;

#pragma unroll 4
    for (int k = 0; k < 128; k++) {
        float4 a0 = *(const float4*)&Ash[k * ASH_STRIDE + tm * 8];
        float4 a1 = *(const float4*)&Ash[k * ASH_STRIDE + tm * 8 + 4];
        float4 w0 = *(const float4*)&Wsh[k * 256 + tn * 8];
        float4 w1 = *(const float4*)&Wsh[k * 256 + tn * 8 + 4];
        float a[8] = {a0.x, a0.y, a0.z, a0.w, a1.x, a1.y, a1.z, a1.w};
        float w[8] = {w0.x, w0.y, w0.z, w0.w, w1.x, w1.y, w1.z, w1.w};
#pragma unroll
        for (int i = 0; i < 8; i++)
#pragma unroll
            for (int j = 0; j < 8; j++) acc[i][j] = fmaf(a[i], w[j], acc[i][j]);
    }

    // Epilogue: tn < 16 -> hm (cols tn*8), tn >= 16 -> hg with sigmoid
    const bool isGate = (tn >= 16);
    float* dst = isGate ? g_hg : g_hm;
    const int col0 = (tn & 15) * 8;
#pragma unroll
    for (int mi = 0; mi < 8; mi++) {
        int row = m0 + tm * 8 + mi;
        if (row >= ROWS) continue;
        float v[8];
#pragma unroll
        for (int j = 0; j < 8; j++) {
            float x = acc[mi][j];
            v[j] = isGate ? (1.f / (1.f + __expf(-x))) : x;
        }
        float4* p = (float4*)&dst[row * DD + col0];
        p[0] = make_float4(v[0], v[1], v[2], v[3]);
        p[1] = make_float4(v[4], v[5], v[6], v[7]);
    }
}

// ---------------------------------------------------------------------------
// Kernel 2: edge scatter. One warp per edge; both batches.
//   agg[b, tgt] += hm[b, src] * rel_emb[rel] * hg[b, src]
// ---------------------------------------------------------------------------
__global__ __launch_bounds__(256) void edge_scatter_kernel(
    const int* __restrict__ esrc,
    const int* __restrict__ etgt,
    const int* __restrict__ erel,
    const float* __restrict__ rel_emb)
{
    const int gw   = (blockIdx.x * blockDim.x + threadIdx.x) >> 5;
    const int lane = threadIdx.x & 31;
    if (gw >= EE) return;

    const int s = esrc[gw];
    const int t = etgt[gw];
    const int r = erel[gw];

    const float4* R4 = (const float4*)rel_emb;
    const float4  rv = R4[r * 32 + lane];
    const float4* HM = (const float4*)g_hm;
    const float4* HG = (const float4*)g_hg;
    float*        AG = g_agg;

#pragma unroll
    for (int b = 0; b < BB; b++) {
        int idx = (b * NN + s) * 32 + lane;
        float4 m = HM[idx];
        float4 g = HG[idx];
        float4 o;
        o.x = m.x * rv.x * g.x;
        o.y = m.y * rv.y * g.y;
        o.z = m.z * rv.z * g.z;
        o.w = m.w * rv.w * g.w;
        float* p = &AG[((b * NN + t) * 32 + lane) * 4];
        asm volatile("red.global.add.v4.f32 [%0], {%1, %2, %3, %4};"
                     :: "l"(p), "f"(o.x), "f"(o.y), "f"(o.z), "f"(o.w)
                     : "memory");
    }
}

// ---------------------------------------------------------------------------
// Kernel 3: update + residual + LayerNorm.
//   upd = [h | agg] @ update_W + b ; x = h + relu(upd) ; out = LN(x)
// GEMM M=ROWS, N=128, K=256 (two K-stages of 128). 256 threads,
// block tile 128x128, thread tile 8x8.
// ---------------------------------------------------------------------------
__global__ __launch_bounds__(256) void update_ln_kernel(
    const float* __restrict__ h,
    const float* __restrict__ update_W,
    const float* __restrict__ update_b,
    const float* __restrict__ ln_gamma,
    const float* __restrict__ ln_beta,
    float* __restrict__ out)
{
    extern __shared__ float sh[];
    float* Ash = sh;                      // [128][132], reused per K-stage, then as Xsh
    float* Wsh = sh + 128 * ASH_STRIDE;   // [256][128]

    const int tid = threadIdx.x;
    const int m0  = blockIdx.x * 128;

    // Load full update_W: 256*128 floats = 8192 float4
    {
        const float4* UW4 = (const float4*)update_W;
        float4* W4 = (float4*)Wsh;
        for (int i = tid; i < 8192; i += 256) W4[i] = UW4[i];
    }

    const int tn = tid & 15;   // 16 col-groups of 8 -> 128 cols
    const int tm = tid >> 4;   // 16 row-groups of 8 -> 128 rows

    float acc[8][8];
#pragma unroll
    for (int i = 0; i < 8; i++)
#pragma unroll
        for (int j = 0; j < 8; j++) acc[i][j] = 0.f;

    for (int s = 0; s < 2; s++) {
        const float4* src4 = (const float4*)(s ? g_agg : h);
        __syncthreads();   // Wsh ready (s=0) / Ash free for reuse (s=1)
        for (int i = tid; i < 128 * 32; i += 256) {
            int m = i >> 5, c = i & 31;
            int row = m0 + m;
            float4 v = (row < ROWS) ? src4[row * 32 + c]
                                    : make_float4(0.f, 0.f, 0.f, 0.f);
            int k = c * 4;
            Ash[(k + 0) * ASH_STRIDE + m] = v.x;
            Ash[(k + 1) * ASH_STRIDE + m] = v.y;
            Ash[(k + 2) * ASH_STRIDE + m] = v.z;
            Ash[(k + 3) * ASH_STRIDE + m] = v.w;
        }
        __syncthreads();

#pragma unroll 4
        for (int k = 0; k < 128; k++) {
            float4 a0 = *(const float4*)&Ash[k * ASH_STRIDE + tm * 8];
            float4 a1 = *(const float4*)&Ash[k * ASH_STRIDE + tm * 8 + 4];
            float4 w0 = *(const float4*)&Wsh[(s * 128 + k) * 128 + tn * 8];
            float4 w1 = *(const float4*)&Wsh[(s * 128 + k) * 128 + tn * 8 + 4];
            float a[8] = {a0.x, a0.y, a0.z, a0.w, a1.x, a1.y, a1.z, a1.w};
            float w[8] = {w0.x, w0.y, w0.z, w0.w, w1.x, w1.y, w1.z, w1.w};
#pragma unroll
            for (int i = 0; i < 8; i++)
#pragma unroll
                for (int j = 0; j < 8; j++) acc[i][j] = fmaf(a[i], w[j], acc[i][j]);
        }
    }

    // Epilogue: x = h + relu(acc + bias) -> Xsh (reusing Ash storage)
    __syncthreads();
    float* Xsh = Ash;   // [128][132] row-major now
    {
        const float4* B4 = (const float4*)update_b;
        float4 b0 = B4[tn * 2];
        float4 b1 = B4[tn * 2 + 1];
        const float4* h4 = (const float4*)h;
#pragma unroll
        for (int mi = 0; mi < 8; mi++) {
            int row = m0 + tm * 8 + mi;
            float4 h0, h1;
            if (row < ROWS) {
                h0 = h4[row * 32 + tn * 2];
                h1 = h4[row * 32 + tn * 2 + 1];
            } else {
                h0 = h1 = make_float4(0.f, 0.f, 0.f, 0.f);
            }
            float x0 = h0.x + fmaxf(acc[mi][0] + b0.x, 0.f);
            float x1 = h0.y + fmaxf(acc[mi][1] + b0.y, 0.f);
            float x2 = h0.z + fmaxf(acc[mi][2] + b0.z, 0.f);
            float x3 = h0.w + fmaxf(acc[mi][3] + b0.w, 0.f);
            float x4 = h1.x + fmaxf(acc[mi][4] + b1.x, 0.f);
            float x5 = h1.y + fmaxf(acc[mi][5] + b1.y, 0.f);
            float x6 = h1.z + fmaxf(acc[mi][6] + b1.z, 0.f);
            float x7 = h1.w + fmaxf(acc[mi][7] + b1.w, 0.f);
            float* xp = &Xsh[(tm * 8 + mi) * ASH_STRIDE + tn * 8];
            *(float4*)&xp[0] = make_float4(x0, x1, x2, x3);
            *(float4*)&xp[4] = make_float4(x4, x5, x6, x7);
        }
    }
    __syncthreads();

    // LayerNorm: 8 warps x 16 rows each
    {
        const int wid  = tid >> 5;
        const int lane = tid & 31;
        const float4 gm = ((const float4*)ln_gamma)[lane];
        const float4 bt = ((const float4*)ln_beta)[lane];
        for (int rr = wid; rr < 128; rr += 8) {
            int row = m0 + rr;
            if (row >= ROWS) continue;
            float4 x = *(const float4*)&Xsh[rr * ASH_STRIDE + lane * 4];
            float sum = x.x + x.y + x.z + x.w;
            float sq  = x.x * x.x + x.y * x.y + x.z * x.z + x.w * x.w;
#pragma unroll
            for (int off = 16; off; off >>= 1) {
                sum += __shfl_xor_sync(0xffffffffu, sum, off);
                sq  += __shfl_xor_sync(0xffffffffu, sq, off);
            }
            float mu  = sum * (1.f / 128.f);
            float var = sq * (1.f / 128.f) - mu * mu;
            float inv = rsqrtf(var + 1e-5f);
            float4 o;
            o.x = (x.x - mu) * inv * gm.x + bt.x;
            o.y = (x.y - mu) * inv * gm.y + bt.y;
            o.z = (x.z - mu) * inv * gm.z + bt.z;
            o.w = (x.w - mu) * inv * gm.w + bt.w;
            ((float4*)out)[row * 32 + lane] = o;
        }
    }
}

// ---------------------------------------------------------------------------
extern "C" void kernel_launch(void* const* d_in, const int* in_sizes, int n_in,
                              void* d_out, int out_size)
{
    const float* h        = (const float*)d_in[0];
    const int*   esrc     = (const int*)d_in[1];
    const int*   etgt     = (const int*)d_in[2];
    const int*   erel     = (const int*)d_in[3];
    // d_in[4] = nE (== NN, unused)
    const float* msg_W    = (const float*)d_in[5];
    const float* rel_emb  = (const float*)d_in[6];
    const float* gate_W   = (const float*)d_in[7];
    const float* update_W = (const float*)d_in[8];
    const float* update_b = (const float*)d_in[9];
    const float* gamma    = (const float*)d_in[10];
    const float* beta     = (const float*)d_in[11];
    float*       out      = (float*)d_out;

    cudaFuncSetAttribute(node_pre_kernel,
                         cudaFuncAttributeMaxDynamicSharedMemorySize, SMEM_BYTES);
    cudaFuncSetAttribute(update_ln_kernel,
                         cudaFuncAttributeMaxDynamicSharedMemorySize, SMEM_BYTES);

    // Zero the scatter-add target
    void* agg_ptr = nullptr;
    cudaGetSymbolAddress(&agg_ptr, g_agg);
    cudaMemsetAsync(agg_ptr, 0, sizeof(float) * ROWS * DD, 0);

    const int gemm_blocks = (ROWS + 127) / 128;   // 782

    node_pre_kernel<<<gemm_blocks, 512, SMEM_BYTES>>>(h, msg_W, gate_W);

    {
        long long total_threads = (long long)EE * 32;
        int blocks = (int)((total_threads + 255) / 256);   // 62500
        edge_scatter_kernel<<<blocks, 256>>>(esrc, etgt, erel, rel_emb);
    }

    update_ln_kernel<<<gemm_blocks, 256, SMEM_BYTES>>>(h, update_W, update_b,
                                                       gamma, beta, out);
}